// round 15
// baseline (speedup 1.0000x reference)
#include <cuda_runtime.h>

#define IMG_W 512
#define IMG_H 512
#define PLANES 64
#define PLANE_STRIDE (IMG_H * IMG_W)
#define NPIX (PLANES * PLANE_STRIDE)
#define STRIP 16
#define STRIPS (IMG_H / STRIP)          // 32
#define NBLOCKS (PLANES * STRIPS)       // 2048
#define EPS 1e-10f

// persistent scratch (statically zero-initialized; reset by last block each call)
__device__ double g_acc;
__device__ unsigned int g_count;

// evict-first streaming load (row data dead after its 3-row window)
__device__ __forceinline__ float4 ldcs4(const float* p) {
    return __ldcs((const float4*)p);
}

__device__ __forceinline__ float process_row(
    const float4& up0, const float4& cen0, const float4& dn0,
    const float4& up1, const float4& cen1, const float4& dn1,
    const float* pr0, const float* pr1,
    bool leftEdge, bool rightEdge, int lane)
{
    // horizontal halo: neighbor lanes via shfl; warp-edge lanes patch with
    // an (L1/L2-hit) scalar load, clamped at image edge
    float hl0 = __shfl_up_sync(0xFFFFFFFFu, cen0.w, 1);
    float hr0 = __shfl_down_sync(0xFFFFFFFFu, cen0.x, 1);
    float hl1 = __shfl_up_sync(0xFFFFFFFFu, cen1.w, 1);
    float hr1 = __shfl_down_sync(0xFFFFFFFFu, cen1.x, 1);
    if (lane == 0) {
        hl0 = leftEdge ? cen0.x : __ldg(pr0 - 1);
        hl1 = leftEdge ? cen1.x : __ldg(pr1 - 1);
    }
    if (lane == 31) {
        hr0 = rightEdge ? cen0.w : __ldg(pr0 + 4);
        hr1 = rightEdge ? cen1.w : __ldg(pr1 + 4);
    }

    // gx = x[min(r+1)] - x[max(r-1)]   (fwd/central/bwd diff)
    const float g0x[4] = { dn0.x - up0.x, dn0.y - up0.y, dn0.z - up0.z, dn0.w - up0.w };
    const float g1x[4] = { dn1.x - up1.x, dn1.y - up1.y, dn1.z - up1.z, dn1.w - up1.w };
    // gy = x[min(c+1)] - x[max(c-1)]
    const float g0y[4] = { cen0.y - hl0, cen0.z - cen0.x, cen0.w - cen0.y, hr0 - cen0.z };
    const float g1y[4] = { cen1.y - hl1, cen1.z - cen1.x, cen1.w - cen1.y, hr1 - cen1.z };

    float a = 0.f, b = 0.f;
#pragma unroll
    for (int i = 0; i < 4; i++) {
        const float n0  = fmaf(g0x[i], g0x[i], fmaf(g0y[i], g0y[i], EPS));
        const float n1  = fmaf(g1x[i], g1x[i], fmaf(g1y[i], g1y[i], EPS));
        const float dot = fmaf(g0x[i], g1x[i], g0y[i] * g1y[i]);
        // dot^2/(n0*n1) == (g0/|g0| . g1/|g1|)^2
        const float v = __fdividef(dot * dot, n0 * n1);
        if (i & 1) b += v; else a += v;
    }
    return a + b;
}

__global__ void __launch_bounds__(128, 9) ngf_kernel(
    const float* __restrict__ I0, const float* __restrict__ I1,
    float* __restrict__ out)
{
    const int t     = threadIdx.x;            // 0..127, one float4 column-group
    const int lane  = t & 31;
    const int plane = blockIdx.x >> 5;        // / STRIPS
    const int strip = blockIdx.x & (STRIPS - 1);
    const int col   = t << 2;                 // 0..508

    const float* __restrict__ p0 = I0 + plane * PLANE_STRIDE + col;
    const float* __restrict__ p1 = I1 + plane * PLANE_STRIDE + col;

    const int rbase = strip * STRIP;
    const int rup   = (rbase > 0) ? rbase - 1 : 0;

    // rolling rows: up = row max(r-1,0), cen = row r, dn = row min(r+1,511)
    float4 up0  = ldcs4(p0 + rup * IMG_W);
    float4 up1  = ldcs4(p1 + rup * IMG_W);
    float4 cen0 = ldcs4(p0 + rbase * IMG_W);
    float4 cen1 = ldcs4(p1 + rbase * IMG_W);
    float4 dn0  = ldcs4(p0 + (rbase + 1) * IMG_W);
    float4 dn1  = ldcs4(p1 + (rbase + 1) * IMG_W);

    const bool leftEdge  = (col == 0);
    const bool rightEdge = (col + 4 == IMG_W);

    float s = 0.f;

    // current-row pointers (also the base for immediate-offset lookahead loads)
    const float* q0 = p0 + rbase * IMG_W;
    const float* q1 = p1 + rbase * IMG_W;

    if (strip != STRIPS - 1) {
        // FAST PATH (strips 0..30): rows r+2, r+3 <= 511 always in range.
        // All lookahead loads are immediate offsets: zero clamp, zero IMAD row math.
#pragma unroll 2
        for (int it = 0; it < STRIP / 2; ++it) {
            const float4 nA0 = ldcs4(q0 + 2 * IMG_W);
            const float4 nA1 = ldcs4(q1 + 2 * IMG_W);
            const float4 nB0 = ldcs4(q0 + 3 * IMG_W);
            const float4 nB1 = ldcs4(q1 + 3 * IMG_W);

            s += process_row(up0, cen0, dn0, up1, cen1, dn1,
                             q0, q1, leftEdge, rightEdge, lane);
            up0 = cen0; cen0 = dn0; dn0 = nA0;
            up1 = cen1; cen1 = dn1; dn1 = nA1;

            s += process_row(up0, cen0, dn0, up1, cen1, dn1,
                             q0 + IMG_W, q1 + IMG_W, leftEdge, rightEdge, lane);
            up0 = cen0; cen0 = dn0; dn0 = nB0;
            up1 = cen1; cen1 = dn1; dn1 = nB1;

            q0 += 2 * IMG_W; q1 += 2 * IMG_W;
        }
    } else {
        // GENERAL PATH (strip 31 only): bottom clamp needed on lookahead rows
#pragma unroll 2
        for (int r = rbase; r < rbase + STRIP; r += 2) {
            int rnA = r + 2; if (rnA > IMG_H - 1) rnA = IMG_H - 1;
            int rnB = r + 3; if (rnB > IMG_H - 1) rnB = IMG_H - 1;
            const float4 nA0 = ldcs4(p0 + rnA * IMG_W);
            const float4 nA1 = ldcs4(p1 + rnA * IMG_W);
            const float4 nB0 = ldcs4(p0 + rnB * IMG_W);
            const float4 nB1 = ldcs4(p1 + rnB * IMG_W);

            s += process_row(up0, cen0, dn0, up1, cen1, dn1,
                             q0, q1, leftEdge, rightEdge, lane);
            up0 = cen0; cen0 = dn0; dn0 = nA0;
            up1 = cen1; cen1 = dn1; dn1 = nA1;

            s += process_row(up0, cen0, dn0, up1, cen1, dn1,
                             q0 + IMG_W, q1 + IMG_W, leftEdge, rightEdge, lane);
            up0 = cen0; cen0 = dn0; dn0 = nB0;
            up1 = cen1; cen1 = dn1; dn1 = nB1;

            q0 += 2 * IMG_W; q1 += 2 * IMG_W;
        }
    }

    // warp reduction
#pragma unroll
    for (int off = 16; off > 0; off >>= 1)
        s += __shfl_xor_sync(0xFFFFFFFFu, s, off);

    __shared__ float warp_part[4];
    const int wid = t >> 5;
    if (lane == 0) warp_part[wid] = s;
    __syncthreads();

    if (t == 0) {
        const double bs = (double)warp_part[0] + (double)warp_part[1]
                        + (double)warp_part[2] + (double)warp_part[3];
        atomicAdd(&g_acc, bs);
        __threadfence();
        const unsigned prev = atomicAdd(&g_count, 1u);
        if (prev == NBLOCKS - 1) {
            // last block: all adds visible (atomics serialize at L2)
            const double total = atomicAdd(&g_acc, 0.0);
            out[0] = (float)(1.0 - total / (double)NPIX);
            // reset for next graph replay (deterministic)
            g_acc = 0.0;
            g_count = 0u;
            __threadfence();
        }
    }
}

extern "C" void kernel_launch(void* const* d_in, const int* in_sizes, int n_in,
                              void* d_out, int out_size)
{
    const float* I0 = (const float*)d_in[0];
    const float* I1 = (const float*)d_in[1];
    float* out = (float*)d_out;

    ngf_kernel<<<NBLOCKS, 128>>>(I0, I1, out);
}

// round 16
// speedup vs baseline: 1.1356x; 1.1356x over previous
#include <cuda_runtime.h>

#define IMG_W 512
#define IMG_H 512
#define PLANES 64
#define PLANE_STRIDE (IMG_H * IMG_W)
#define NPIX (PLANES * PLANE_STRIDE)
#define STRIP 16
#define STRIPS (IMG_H / STRIP)          // 32
#define NBLOCKS (PLANES * STRIPS)       // 2048
#define EPS 1e-10f

// persistent scratch (statically zero-initialized; reset by last block each call)
__device__ double g_acc;
__device__ unsigned int g_count;

// evict-first streaming load (row data dead after its 3-row window)
__device__ __forceinline__ float4 ldcs4(const float* p) {
    return __ldcs((const float4*)p);
}

__device__ __forceinline__ float process_row(
    const float4& up0, const float4& cen0, const float4& dn0,
    const float4& up1, const float4& cen1, const float4& dn1,
    const float* pr0, const float* pr1,
    bool leftEdge, bool rightEdge, int lane)
{
    // horizontal halo: neighbor lanes via shfl; warp-edge lanes patch with
    // an (L1/L2-hit) scalar load, clamped at image edge
    float hl0 = __shfl_up_sync(0xFFFFFFFFu, cen0.w, 1);
    float hr0 = __shfl_down_sync(0xFFFFFFFFu, cen0.x, 1);
    float hl1 = __shfl_up_sync(0xFFFFFFFFu, cen1.w, 1);
    float hr1 = __shfl_down_sync(0xFFFFFFFFu, cen1.x, 1);
    if (lane == 0) {
        hl0 = leftEdge ? cen0.x : __ldg(pr0 - 1);
        hl1 = leftEdge ? cen1.x : __ldg(pr1 - 1);
    }
    if (lane == 31) {
        hr0 = rightEdge ? cen0.w : __ldg(pr0 + 4);
        hr1 = rightEdge ? cen1.w : __ldg(pr1 + 4);
    }

    // gx = x[min(r+1)] - x[max(r-1)]   (fwd/central/bwd diff)
    const float g0x[4] = { dn0.x - up0.x, dn0.y - up0.y, dn0.z - up0.z, dn0.w - up0.w };
    const float g1x[4] = { dn1.x - up1.x, dn1.y - up1.y, dn1.z - up1.z, dn1.w - up1.w };
    // gy = x[min(c+1)] - x[max(c-1)]
    const float g0y[4] = { cen0.y - hl0, cen0.z - cen0.x, cen0.w - cen0.y, hr0 - cen0.z };
    const float g1y[4] = { cen1.y - hl1, cen1.z - cen1.x, cen1.w - cen1.y, hr1 - cen1.z };

    float a = 0.f, b = 0.f;
#pragma unroll
    for (int i = 0; i < 4; i++) {
        const float n0  = fmaf(g0x[i], g0x[i], fmaf(g0y[i], g0y[i], EPS));
        const float n1  = fmaf(g1x[i], g1x[i], fmaf(g1y[i], g1y[i], EPS));
        const float dot = fmaf(g0x[i], g1x[i], g0y[i] * g1y[i]);
        // dot^2/(n0*n1) == (g0/|g0| . g1/|g1|)^2
        const float v = __fdividef(dot * dot, n0 * n1);
        if (i & 1) b += v; else a += v;
    }
    return a + b;
}

__global__ void __launch_bounds__(128) ngf_kernel(
    const float* __restrict__ I0, const float* __restrict__ I1,
    float* __restrict__ out)
{
    const int t     = threadIdx.x;            // 0..127, one float4 column-group
    const int lane  = t & 31;
    const int plane = blockIdx.x >> 5;        // / STRIPS
    const int strip = blockIdx.x & (STRIPS - 1);
    const int col   = t << 2;                 // 0..508

    const float* __restrict__ p0 = I0 + plane * PLANE_STRIDE + col;
    const float* __restrict__ p1 = I1 + plane * PLANE_STRIDE + col;

    const int rbase = strip * STRIP;
    const int rup   = (rbase > 0) ? rbase - 1 : 0;

    // rolling rows: up = row max(r-1,0), cen = row r, dn = row min(r+1,511)
    float4 up0  = ldcs4(p0 + rup * IMG_W);
    float4 up1  = ldcs4(p1 + rup * IMG_W);
    float4 cen0 = ldcs4(p0 + rbase * IMG_W);
    float4 cen1 = ldcs4(p1 + rbase * IMG_W);
    float4 dn0  = ldcs4(p0 + (rbase + 1) * IMG_W);
    float4 dn1  = ldcs4(p1 + (rbase + 1) * IMG_W);

    const bool leftEdge  = (col == 0);
    const bool rightEdge = (col + 4 == IMG_W);

    float s = 0.f;

    // current-row pointers (also the base for immediate-offset lookahead loads)
    const float* q0 = p0 + rbase * IMG_W;
    const float* q1 = p1 + rbase * IMG_W;

    if (strip != STRIPS - 1) {
        // FAST PATH (strips 0..30): rows r+2, r+3 <= 511 always in range.
        // All lookahead loads are immediate offsets: zero clamp, zero IMAD row math.
        // unroll 4 => 8-row straight-line body, front-batched lookahead LDGs.
#pragma unroll 4
        for (int it = 0; it < STRIP / 2; ++it) {
            const float4 nA0 = ldcs4(q0 + 2 * IMG_W);
            const float4 nA1 = ldcs4(q1 + 2 * IMG_W);
            const float4 nB0 = ldcs4(q0 + 3 * IMG_W);
            const float4 nB1 = ldcs4(q1 + 3 * IMG_W);

            s += process_row(up0, cen0, dn0, up1, cen1, dn1,
                             q0, q1, leftEdge, rightEdge, lane);
            up0 = cen0; cen0 = dn0; dn0 = nA0;
            up1 = cen1; cen1 = dn1; dn1 = nA1;

            s += process_row(up0, cen0, dn0, up1, cen1, dn1,
                             q0 + IMG_W, q1 + IMG_W, leftEdge, rightEdge, lane);
            up0 = cen0; cen0 = dn0; dn0 = nB0;
            up1 = cen1; cen1 = dn1; dn1 = nB1;

            q0 += 2 * IMG_W; q1 += 2 * IMG_W;
        }
    } else {
        // GENERAL PATH (strip 31 only): bottom clamp needed on lookahead rows
#pragma unroll 2
        for (int r = rbase; r < rbase + STRIP; r += 2) {
            int rnA = r + 2; if (rnA > IMG_H - 1) rnA = IMG_H - 1;
            int rnB = r + 3; if (rnB > IMG_H - 1) rnB = IMG_H - 1;
            const float4 nA0 = ldcs4(p0 + rnA * IMG_W);
            const float4 nA1 = ldcs4(p1 + rnA * IMG_W);
            const float4 nB0 = ldcs4(p0 + rnB * IMG_W);
            const float4 nB1 = ldcs4(p1 + rnB * IMG_W);

            s += process_row(up0, cen0, dn0, up1, cen1, dn1,
                             q0, q1, leftEdge, rightEdge, lane);
            up0 = cen0; cen0 = dn0; dn0 = nA0;
            up1 = cen1; cen1 = dn1; dn1 = nA1;

            s += process_row(up0, cen0, dn0, up1, cen1, dn1,
                             q0 + IMG_W, q1 + IMG_W, leftEdge, rightEdge, lane);
            up0 = cen0; cen0 = dn0; dn0 = nB0;
            up1 = cen1; cen1 = dn1; dn1 = nB1;

            q0 += 2 * IMG_W; q1 += 2 * IMG_W;
        }
    }

    // warp reduction
#pragma unroll
    for (int off = 16; off > 0; off >>= 1)
        s += __shfl_xor_sync(0xFFFFFFFFu, s, off);

    __shared__ float warp_part[4];
    const int wid = t >> 5;
    if (lane == 0) warp_part[wid] = s;
    __syncthreads();

    if (t == 0) {
        const double bs = (double)warp_part[0] + (double)warp_part[1]
                        + (double)warp_part[2] + (double)warp_part[3];
        atomicAdd(&g_acc, bs);
        __threadfence();
        const unsigned prev = atomicAdd(&g_count, 1u);
        if (prev == NBLOCKS - 1) {
            // last block: all adds visible (atomics serialize at L2)
            const double total = atomicAdd(&g_acc, 0.0);
            out[0] = (float)(1.0 - total / (double)NPIX);
            // reset for next graph replay (deterministic)
            g_acc = 0.0;
            g_count = 0u;
            __threadfence();
        }
    }
}

extern "C" void kernel_launch(void* const* d_in, const int* in_sizes, int n_in,
                              void* d_out, int out_size)
{
    const float* I0 = (const float*)d_in[0];
    const float* I1 = (const float*)d_in[1];
    float* out = (float*)d_out;

    ngf_kernel<<<NBLOCKS, 128>>>(I0, I1, out);
}